// round 4
// baseline (speedup 1.0000x reference)
#include <cuda_runtime.h>
#include <stdint.h>

#define D_DIM   10000
#define T_STEPS 2048
#define TN      2046            /* ngram terms */
#define ROWPW   2512            /* padded table row: 10048 cols = 2512 words */
#define GROUPS  81              /* column groups, stride 124, window 128 */
#define SSPLIT  6               /* t-splits per group */
#define TCHUNK  341             /* 2046 / 6 */
#define WCH     22              /* ceil(341/16) steps per warp */
#define NG_SMEM (12800*4 + 128*4)

#define INIT_BLOCKS 3925        /* 3925*256 = 1,004,800 = 400*ROWPW exactly */
#define COMB_BLOCKS 1250        /* 8 d per block */

/* {0,1} tables: row = c*100+l, padded 10048 cols (cols>=10000 mirror 0..47) */
__device__ uint32_t g_tab[400 * ROWPW];           /* ~4.02 MB */
__device__ uint4    g_idx4[T_STEPS];              /* per-t smem word offsets, 4 channels */
__device__ float    g_sample[D_DIM];
__device__ float    g_comb[D_DIM];

__constant__ int c_featIdx[29] = {
    546,547,548,550,553,555,556,557,558,559,560,561,562,564,
    565,566,569,575,579,580,581,582,583,584,587,592,597,598,599
};

/* ---------- kernel A: fused (table/idx/zero init)  +  (comb precompute) ---------- */
__global__ void __launch_bounds__(256) k_fused(const float* __restrict__ signals,
                                               const float* __restrict__ keys,
                                               const float* __restrict__ lw,
                                               const float* __restrict__ feat,
                                               const float* __restrict__ feat_w,
                                               const float* __restrict__ feat_b,
                                               const float* __restrict__ mfcc_w,
                                               const float* __restrict__ mfcc_b)
{
    __shared__ float s_feat[600];
    __shared__ float s_fh[8][32];

    const int tid = threadIdx.x;
    const int bid = blockIdx.x;

    /* interleave 3 init : 1 comb for DRAM/ALU overlap */
    int initId = -1, combId = -1;
    if (bid < 5000) {
        const int g = bid >> 2, r = bid & 3;
        if (r == 3) combId = g; else initId = g * 3 + r;
    } else {
        initId = 3750 + (bid - 5000);
    }

    if (initId >= 0) {
        const int j = initId * 256 + tid;       /* j < 1,004,800 always */

        if (j < D_DIM) g_sample[j] = 0.0f;

        if (j < T_STEPS) {
            int l[4];
#pragma unroll
            for (int c = 0; c < 4; ++c) {
                float s = signals[j * 4 + c];
                s = fminf(fmaxf(s, 0.0f), 1.0f);
                int v = (int)rintf(s * 99.0f);  /* round-half-even == jnp.round */
                l[c] = min(max(v, 0), 99);
            }
            g_idx4[j] = make_uint4(l[0]*32, 3200 + l[1]*32, 6400 + l[2]*32, 9600 + l[3]*32);
        }

        /* one thread per (channel,row,word): byte = (sign(k)==sign(w)) ? 1 : 0 */
        const int w   = j % ROWPW;
        const int row = j / ROWPW;              /* 0..399 = c*100 + l */
        const int c   = row / 100;
        const int l   = row - c * 100;
        const int dd  = w * 4;
        const int dsrc = (dd >= D_DIM) ? dd - D_DIM : dd;

        const float4 wf = *(const float4*)(lw + l * D_DIM + dsrc);
        const float4 kf = *(const float4*)(keys + c * D_DIM + dsrc);

        const uint32_t b0 = (~(__float_as_uint(kf.x) ^ __float_as_uint(wf.x))) >> 31;
        const uint32_t b1 = (~(__float_as_uint(kf.y) ^ __float_as_uint(wf.y))) >> 31;
        const uint32_t b2 = (~(__float_as_uint(kf.z) ^ __float_as_uint(wf.z))) >> 31;
        const uint32_t b3 = (~(__float_as_uint(kf.w) ^ __float_as_uint(wf.w))) >> 31;
        g_tab[row * ROWPW + w] = b0 | (b1 << 8) | (b2 << 16) | (b3 << 24);
    } else {
        /* ---- comb precompute: 8 warps, one d each ---- */
        for (int i = tid; i < 600; i += 256) s_feat[i] = feat[i];
        __syncthreads();

        const int warpId = tid >> 5;
        const int lane   = tid & 31;
        const int d      = combId * 8 + warpId;
        if (d >= D_DIM) return;

        float prod = 1.0f;
#pragma unroll
        for (int k = 0; k < 6; ++k) {
            const float* wrow = mfcc_w + (k * D_DIM + d) * 91;
            float a = 0.0f;
            if (lane < 27) a += wrow[64 + lane] * s_feat[k * 91 + 64 + lane];
            a += wrow[32 + lane] * s_feat[k * 91 + 32 + lane];
            a += wrow[lane]      * s_feat[k * 91 + lane];
#pragma unroll
            for (int off = 16; off; off >>= 1) a += __shfl_xor_sync(0xffffffffu, a, off);
            const float b = mfcc_b[k * D_DIM + d];
            prod *= cosf(a + b) * sinf(a);
        }

        float fh = 0.0f;
        if (lane < 29) {
            const float sv = s_feat[c_featIdx[lane]];
            const float pw = sv * feat_w[lane * D_DIM + d];
            fh = cosf(pw + feat_b[lane * D_DIM + d]) * sinf(pw);
        }
        s_fh[warpId][lane] = fh;
        __syncwarp();

        if (lane == 0) {
            const float* f = s_fh[warpId];
            g_comb[d] =
                  f[0]  * f[8]  * f[13]
                + f[1]  * f[9]  * f[14]
                + f[2]  * f[10] * f[15]
                + f[3]  * f[4]
                + f[5]  * f[7]  * f[22] * f[6]  * f[23] * f[19] * f[18]
                        * f[20] * f[21] * f[26] * f[28] * f[27]
                + f[11] + f[12]
                + f[16] * f[24]
                + f[17] + f[25]
                + prod;
        }
    }
}

/* ---------- kernel B: per_t + ngram + multiset sum ({0,1} byte path) ---------- */
__global__ void __launch_bounds__(512) k_ngram()
{
    extern __shared__ uint32_t smem[];
    uint32_t* s_tab = smem;                 /* 12800 words = 4 planes x 100 x 32 */
    int*      s_acc = (int*)(smem + 12800); /* 128 per-window-column accumulators */

    const int tid  = threadIdx.x;
    const int g    = blockIdx.x / SSPLIT;
    const int s    = blockIdx.x % SSPLIT;
    const int gw   = g * 31;                /* window start, words */

    /* stage window: 400 rows x 32 words, coalesced */
    for (int w = tid; w < 12800; w += 512) {
        const int row = w >> 5;
        s_tab[w] = g_tab[row * ROWPW + gw + (w & 31)];
    }
    if (tid < 128) s_acc[tid] = 0;
    __syncthreads();

    const int warp = tid >> 5;
    const int lane = tid & 31;
    const int t0 = s * TCHUNK + warp * WCH;
    const int t1 = min(t0 + WCH, (s + 1) * TCHUNK);

    if (t0 < t1) {
        int a2x, a2y, a2z, a2w;             /* s2 @ t-2 */
        int b2x, b2y, b2z, b2w;             /* s2 @ t-1 */
        int b1x, b1y, b1z, b1w;             /* s1 @ t-1 */
        int ax = 0, ay = 0, az = 0, aw = 0; /* accumulators */

        /* per_t = 2s-4; we carry v = s-2 (dp4a acc = -2), scale x8 at the end */
#define NG_STEP(ROW, V0,V1,V2,V3, S1X,S1Y,S1Z,S1W, S2X,S2Y,S2Z,S2W)            \
        {                                                                       \
            const uint4 ix = g_idx4[ROW];                                       \
            const uint32_t u0 = s_tab[ix.x + lane];                             \
            const uint32_t u1 = s_tab[ix.y + lane];                             \
            const uint32_t u2 = s_tab[ix.z + lane];                             \
            const uint32_t u3 = s_tab[ix.w + lane];                             \
            const uint32_t sm4 = (u0 + u1) + (u2 + u3); /* byte sums <= 4 */    \
            V0 = __dp4a((int)sm4, 0x00000001, -2);                              \
            V1 = __dp4a((int)sm4, 0x00000100, -2);                              \
            V2 = __dp4a((int)sm4, 0x00010000, -2);                              \
            V3 = __dp4a((int)sm4, 0x01000000, -2);                              \
            const int n3 = __shfl_up_sync(0xffffffffu, V3, 1);                  \
            const int n2 = __shfl_up_sync(0xffffffffu, V2, 1);                  \
            S1X = n3; S1Y = V0; S1Z = V1; S1W = V2;                             \
            S2X = n2; S2Y = n3; S2Z = V0; S2W = V1;                             \
        }

        {   /* warm-up rows t0, t0+1 */
            int v0,v1,v2,v3, d1x,d1y,d1z,d1w;
            NG_STEP(t0,     v0,v1,v2,v3, d1x,d1y,d1z,d1w, a2x,a2y,a2z,a2w);
            NG_STEP(t0 + 1, v0,v1,v2,v3, b1x,b1y,b1z,b1w, b2x,b2y,b2z,b2w);
        }

#pragma unroll 2
        for (int t = t0 + 2; t < t1 + 2; ++t) {
            int v0,v1,v2,v3, c1x,c1y,c1z,c1w, c2x,c2y,c2z,c2w;
            NG_STEP(t, v0,v1,v2,v3, c1x,c1y,c1z,c1w, c2x,c2y,c2z,c2w);
            ax += a2x * b1x * v0;
            ay += a2y * b1y * v1;
            az += a2z * b1z * v2;
            aw += a2w * b1w * v3;
            a2x = b2x; a2y = b2y; a2z = b2z; a2w = b2w;
            b2x = c2x; b2y = c2y; b2z = c2z; b2w = c2w;
            b1x = c1x; b1y = c1y; b1z = c1z; b1w = c1w;
        }
#undef NG_STEP

        atomicAdd(&s_acc[4*lane + 0], ax);
        atomicAdd(&s_acc[4*lane + 1], ay);
        atomicAdd(&s_acc[4*lane + 2], az);
        atomicAdd(&s_acc[4*lane + 3], aw);
    }

    __syncthreads();
    /* window positions 2..125 -> global (wrap group keeps o <= D+1); x8 restores scale */
    if (tid >= 2 && tid < 126) {
        int o = g * 124 + tid;
        if (o <= D_DIM + 1) {
            if (o >= D_DIM) o -= D_DIM;
            atomicAdd(&g_sample[o], (float)(s_acc[tid] * 8));
        }
    }
}

/* ---------- kernel C: final bind + hard quantize ---------- */
__global__ void __launch_bounds__(256) k_sign(float* __restrict__ out)
{
    const int d = blockIdx.x * 256 + threadIdx.x;
    if (d < D_DIM)
        out[d] = (g_sample[d] * g_comb[d] > 0.0f) ? 1.0f : -1.0f;
}

/* ---------- launcher ---------- */
extern "C" void kernel_launch(void* const* d_in, const int* in_sizes, int n_in,
                              void* d_out, int out_size)
{
    (void)in_sizes; (void)n_in; (void)out_size;
    const float* signals = (const float*)d_in[0];
    const float* feat    = (const float*)d_in[1];
    const float* keys    = (const float*)d_in[2];
    const float* lw      = (const float*)d_in[3];
    const float* fw      = (const float*)d_in[4];
    const float* fb      = (const float*)d_in[5];
    const float* mw      = (const float*)d_in[6];
    const float* mb      = (const float*)d_in[7];
    float* out = (float*)d_out;

    cudaFuncSetAttribute(k_ngram, cudaFuncAttributeMaxDynamicSharedMemorySize, NG_SMEM);

    k_fused<<<INIT_BLOCKS + COMB_BLOCKS, 256>>>(signals, keys, lw, feat, fw, fb, mw, mb);
    k_ngram<<<GROUPS * SSPLIT, 512, NG_SMEM>>>();
    k_sign<<<40, 256>>>(out);
}